// round 12
// baseline (speedup 1.0000x reference)
#include <cuda_runtime.h>
#include <cuda_fp16.h>
#include <stdint.h>

#define M_ROWS   8192
#define DM       768
#define NF       16384
#define TOPK     64
#define TOPC     128
#define KDIM     768
#define CAND_MAX 1024
#define PB_CAP   2048

// ---------------- scratch (__device__ globals; no allocs) ----------------
__device__ __align__(256) __half g_A[M_ROWS * KDIM];   // 12.6 MB
__device__ __align__(256) __half g_B[NF     * KDIM];   // 25.2 MB

// ---------------- helpers ----------------
__device__ __forceinline__ uint32_t smem_u32(const void* p) {
    uint32_t a;
    asm("{ .reg .u64 t; cvta.to.shared.u64 t, %1; cvt.u32.u64 %0, t; }" : "=r"(a) : "l"(p));
    return a;
}
__device__ __forceinline__ void cp_async16(uint32_t dst, const void* src) {
    asm volatile("cp.async.cg.shared.global [%0], [%1], 16;" :: "r"(dst), "l"(src));
}
#define CP_COMMIT() asm volatile("cp.async.commit_group;" ::: "memory")
#define CP_WAIT(n)  asm volatile("cp.async.wait_group %0;" :: "n"(n) : "memory")

__device__ __forceinline__ void mma16816(float* c,
                                         uint32_t a0, uint32_t a1, uint32_t a2, uint32_t a3,
                                         uint32_t b0, uint32_t b1) {
    asm volatile("mma.sync.aligned.m16n8k16.row.col.f32.f16.f16.f32 "
        "{%0,%1,%2,%3}, {%4,%5,%6,%7}, {%8,%9}, {%0,%1,%2,%3};"
        : "+f"(c[0]), "+f"(c[1]), "+f"(c[2]), "+f"(c[3])
        : "r"(a0), "r"(a1), "r"(a2), "r"(a3), "r"(b0), "r"(b1));
}
__device__ __forceinline__ void ldsm_x4(uint32_t& r0, uint32_t& r1,
                                        uint32_t& r2, uint32_t& r3, uint32_t addr) {
    asm volatile("ldmatrix.sync.aligned.m8n8.x4.shared.b16 {%0,%1,%2,%3}, [%4];"
        : "=r"(r0), "=r"(r1), "=r"(r2), "=r"(r3) : "r"(addr));
}
__device__ __forceinline__ void ldsm_x2(uint32_t& r0, uint32_t& r1, uint32_t addr) {
    asm volatile("ldmatrix.sync.aligned.m8n8.x2.shared.b16 {%0,%1}, [%2];"
        : "=r"(r0), "=r"(r1) : "r"(addr));
}
__device__ __forceinline__ unsigned fkey(unsigned b) {
    return (b & 0x80000000u) ? ~b : (b | 0x80000000u);
}

// ============================================================
// convert: fp32 -> fp16, vectorized x4
// ============================================================
__global__ void convert_x_kernel(const float* __restrict__ x) {
    int i = blockIdx.x * blockDim.x + threadIdx.x;
    if (i >= M_ROWS * KDIM / 4) return;
    float4 v = ((const float4*)x)[i];
    ((__half2*)g_A)[i * 2]     = __floats2half2_rn(v.x, v.y);
    ((__half2*)g_A)[i * 2 + 1] = __floats2half2_rn(v.z, v.w);
}
__global__ void convert_w_kernel(const float* __restrict__ w) {
    int i = blockIdx.x * blockDim.x + threadIdx.x;
    if (i >= NF * KDIM / 4) return;
    float4 v = ((const float4*)w)[i];
    ((__half2*)g_B)[i * 2]     = __floats2half2_rn(v.x, v.y);
    ((__half2*)g_B)[i * 2 + 1] = __floats2half2_rn(v.z, v.w);
}

// ============================================================
// mma.sync fp16 GEMM, 4-stage watertight pipeline + ldmatrix
// (R10 variant: passed correctness, ~60us faster than R9)
// ============================================================
#define BM 128
#define BN 128
#define BK 32
#define STAGES 4
#define ROWB 80
#define STG (256 * ROWB)
#define GEMM_SMEM (STAGES * STG)       // 81920 B
#define KITERS (KDIM / BK)             // 24

__global__ __launch_bounds__(256, 2)
void gemm_mma_kernel(const float* __restrict__ bias, float* __restrict__ pre) {
    extern __shared__ char sm[];
    const uint32_t sb = smem_u32(sm);
    const int tid = threadIdx.x;
    const int wid = tid >> 5;
    const int lane = tid & 31;
    const int g   = lane >> 2;
    const int tig = lane & 3;
    const int bm = blockIdx.x * BM;
    const int bn = blockIdx.y * BN;
    const int wm = (wid >> 2) * 64;
    const int wn = (wid & 3) * 32;

    const __half* Ag = g_A + (size_t)bm * KDIM;
    const __half* Bg = g_B + (size_t)bn * KDIM;

    float acc[4][4][4];
#pragma unroll
    for (int mi = 0; mi < 4; mi++)
#pragma unroll
        for (int ni = 0; ni < 4; ni++)
#pragma unroll
            for (int q = 0; q < 4; q++) acc[mi][ni][q] = 0.f;

    const int lr0 = tid >> 2;
    const int lr1 = (tid + 256) >> 2;
    const int lc  = tid & 3;

    auto issue = [&](int s) {
        const uint32_t base = sb + (s % STAGES) * STG;
        const size_t k0 = (size_t)s * BK;
        cp_async16(base + lr0 * ROWB + lc * 16, Ag + (size_t)lr0 * KDIM + k0 + lc * 8);
        cp_async16(base + lr1 * ROWB + lc * 16, Ag + (size_t)lr1 * KDIM + k0 + lc * 8);
        const uint32_t bb = base + 128 * ROWB;
        cp_async16(bb + lr0 * ROWB + lc * 16, Bg + (size_t)lr0 * KDIM + k0 + lc * 8);
        cp_async16(bb + lr1 * ROWB + lc * 16, Bg + (size_t)lr1 * KDIM + k0 + lc * 8);
    };

    issue(0); CP_COMMIT();
    issue(1); CP_COMMIT();
    issue(2); CP_COMMIT();

    const uint32_t a_lrow = (uint32_t)(lane & 15) * ROWB + ((lane >> 4) & 1) * 16;
    const uint32_t b_lrow = (uint32_t)(lane & 7)  * ROWB + ((lane >> 3) & 1) * 16;

    for (int kb = 0; kb < KITERS; kb++) {
        if (kb + 3 < KITERS) issue(kb + 3);
        CP_COMMIT();
        CP_WAIT(3);
        __syncthreads();

        const uint32_t abase = sb + (kb % STAGES) * STG;
        const uint32_t bbase = abase + 128 * ROWB;
#pragma unroll
        for (int kk = 0; kk < 2; kk++) {
            uint32_t bfr[4][2];
#pragma unroll
            for (int ni = 0; ni < 4; ni++)
                ldsm_x2(bfr[ni][0], bfr[ni][1],
                        bbase + (wn + ni * 8) * ROWB + kk * 32 + b_lrow);
#pragma unroll
            for (int mi = 0; mi < 4; mi++) {
                uint32_t a0, a1, a2, a3;
                ldsm_x4(a0, a1, a2, a3,
                        abase + (wm + mi * 16) * ROWB + kk * 32 + a_lrow);
#pragma unroll
                for (int ni = 0; ni < 4; ni++)
                    mma16816(acc[mi][ni], a0, a1, a2, a3, bfr[ni][0], bfr[ni][1]);
            }
        }
        __syncthreads();
    }

#pragma unroll
    for (int ni = 0; ni < 4; ni++) {
        const int col = bn + wn + ni * 8 + tig * 2;
        float2 bz = *(const float2*)(bias + col);
#pragma unroll
        for (int mi = 0; mi < 4; mi++) {
            const int r0 = bm + wm + mi * 16 + g;
            float2 v0, v1;
            v0.x = acc[mi][ni][0] + bz.x; v0.y = acc[mi][ni][1] + bz.y;
            v1.x = acc[mi][ni][2] + bz.x; v1.y = acc[mi][ni][3] + bz.y;
            *(float2*)(pre + (size_t)r0 * NF + col)       = v0;
            *(float2*)(pre + (size_t)(r0 + 8) * NF + col) = v1;
        }
    }
}

// ============================================================
// FUSED post-GEMM v4 (one block/row):
//   p1: stream pre (float4) -> coarse 12-bit hist
//   p2: pivot scan -> pv1, chi, cb
//   p3: one float4 re-read: direct candidates (b>pv1), stage
//       pivot-bin ties in smem + fine 12-bit hist (bits 8..19)
//   p4: in-smem refinement -> C ~ 130 candidates
//   p5: exact fp32 rescore (ascending-k fmaf chain, validated)
//   p6: zero codes row; rank; scatter; sparse decode (float4)
// ============================================================
__global__ __launch_bounds__(256)
void postgemm_kernel(const float* __restrict__ pre,
                     const float* __restrict__ x,
                     const float* __restrict__ Wenc,
                     const float* __restrict__ benc,
                     const float* __restrict__ Dm,
                     float* __restrict__ codes,
                     float* __restrict__ recon) {
    __shared__ float          xs[DM];
    __shared__ unsigned       hist[4096];
    __shared__ unsigned       skey[PB_CAP];
    __shared__ unsigned short spbi[PB_CAP];
    __shared__ float          sval[CAND_MAX];
    __shared__ int            sidxA[CAND_MAX];
    __shared__ int            cidx[CAND_MAX];
    __shared__ int            stki[TOPK];
    __shared__ float          stkv[TOPK];
    __shared__ unsigned       wsum[8];
    __shared__ unsigned       s_pv, s_chi, s_cnt, s_pbc;

    const int row = blockIdx.x;
    const int tid = threadIdx.x;
    const int wid = tid >> 5;
    const int lane = tid & 31;
    const float4* p4 = (const float4*)(pre + (size_t)row * NF);

    // ---- p1: zero hist; coarse hist over keys; load x ----
#pragma unroll
    for (int q = 0; q < 16; q++) hist[tid + q * 256] = 0u;
    if (tid == 0) { s_cnt = 0u; s_pbc = 0u; }
    __syncthreads();

    for (int i = tid; i < NF / 4; i += 256) {
        float4 v = p4[i];
        atomicAdd(&hist[fkey(__float_as_uint(v.x)) >> 20], 1u);
        atomicAdd(&hist[fkey(__float_as_uint(v.y)) >> 20], 1u);
        atomicAdd(&hist[fkey(__float_as_uint(v.z)) >> 20], 1u);
        atomicAdd(&hist[fkey(__float_as_uint(v.w)) >> 20], 1u);
    }
    for (int i = tid; i < DM; i += 256) xs[i] = x[(size_t)row * DM + i];
    __syncthreads();

    // ---- pivot scan over 4096 bins, descending ----
    auto pivot4096 = [&](unsigned want) {
        unsigned h[16], csum = 0;
        const int hi = 4095 - 16 * tid;
#pragma unroll
        for (int q = 0; q < 16; q++) { h[q] = hist[hi - q]; csum += h[q]; }
        unsigned incl = csum;
#pragma unroll
        for (int o = 1; o < 32; o <<= 1) {
            unsigned n = __shfl_up_sync(0xffffffffu, incl, o);
            if (lane >= o) incl += n;
        }
        if (lane == 31) wsum[wid] = incl;
        __syncthreads();
        if (wid == 0 && lane < 8) {
            unsigned w = wsum[lane];
#pragma unroll
            for (int o = 1; o < 8; o <<= 1) {
                unsigned n = __shfl_up_sync(0x000000ffu, w, o);
                if (lane >= o) w += n;
            }
            wsum[lane] = w;
        }
        __syncthreads();
        incl += (wid > 0 ? wsum[wid - 1] : 0u);
        unsigned excl = incl - csum;
        if (excl < want && want <= incl) {
            unsigned run = excl;
#pragma unroll
            for (int q = 0; q < 16; q++) {
                if (run < want && want <= run + h[q]) {
                    s_pv = (unsigned)(hi - q);
                    s_chi = run;
                }
                run += h[q];
            }
        }
        __syncthreads();
    };

    pivot4096(TOPC);
    const unsigned pv1 = s_pv;
    const unsigned chi = s_chi;            // strictly above pivot bin (< TOPC)
    const unsigned cb  = hist[pv1];        // pivot-bin count
    __syncthreads();

    // ---- p3: zero hist (reuse for fine); collect pass ----
#pragma unroll
    for (int q = 0; q < 16; q++) hist[tid + q * 256] = 0u;
    __syncthreads();

    for (int i = tid; i < NF / 4; i += 256) {
        float4 v = p4[i];
        unsigned kk[4];
        kk[0] = fkey(__float_as_uint(v.x));
        kk[1] = fkey(__float_as_uint(v.y));
        kk[2] = fkey(__float_as_uint(v.z));
        kk[3] = fkey(__float_as_uint(v.w));
#pragma unroll
        for (int c = 0; c < 4; c++) {
            unsigned k = kk[c], b = k >> 20;
            int idx = i * 4 + c;
            if (b > pv1) {
                cidx[atomicAdd(&s_cnt, 1u)] = idx;           // < TOPC slots
            } else if (b == pv1) {
                unsigned s = atomicAdd(&s_pbc, 1u);
                if (s < PB_CAP) { skey[s] = k; spbi[s] = (unsigned short)idx; }
                atomicAdd(&hist[(k >> 8) & 0xfffu], 1u);
            }
        }
    }
    __syncthreads();
    const unsigned pbc = s_pbc;

    // ---- p4: refinement (in smem) ----
    if (pbc > PB_CAP) {
        // ~12-sigma fallback: re-scan global, take all b >= pv1 (capped)
        for (int i = tid; i < NF; i += 256) {
            unsigned k = fkey(__float_as_uint(pre[(size_t)row * NF + i]));
            if ((k >> 20) == pv1) {
                unsigned s = atomicAdd(&s_cnt, 1u);
                if (s < CAND_MAX) cidx[s] = i;
            }
        }
    } else if (chi + cb <= 192) {
        // small tie set: take whole pivot bin, no refinement
        for (unsigned s = tid; s < cb; s += 256) cidx[chi + s] = (int)spbi[s];
        if (tid == 0) s_cnt = chi + cb;
    } else {
        // fine pivot over mantissa bits 8..19 (bin width ~1e-4)
        pivot4096(TOPC - chi);
        const unsigned pv2 = s_pv;
        __syncthreads();
        for (unsigned s = tid; s < cb; s += 256) {
            if (((skey[s] >> 8) & 0xfffu) >= pv2) {
                unsigned t = atomicAdd(&s_cnt, 1u);
                if (t < CAND_MAX) cidx[t] = (int)spbi[s];
            }
        }
    }
    __syncthreads();
    const int C = (int)min(s_cnt, (unsigned)CAND_MAX);

    // ---- p5: exact fp32 rescore (validated ascending-k chain) ----
    for (int j = tid; j < C; j += 256) {
        const int idx = cidx[j];
        const float4* wr = (const float4*)(Wenc + (size_t)idx * DM);
        float acc = 0.f;
#pragma unroll 4
        for (int q = 0; q < DM / 4; q++) {
            float4 w = wr[q];
            acc = fmaf(xs[q * 4 + 0], w.x, acc);
            acc = fmaf(xs[q * 4 + 1], w.y, acc);
            acc = fmaf(xs[q * 4 + 2], w.z, acc);
            acc = fmaf(xs[q * 4 + 3], w.w, acc);
        }
        sval[j] = acc + benc[idx];
        sidxA[j] = idx;
    }

    // ---- p6a: zero codes row ----
    {
        float4* crow = (float4*)(codes + (size_t)row * NF);
        float4 z = make_float4(0.f, 0.f, 0.f, 0.f);
        for (int i = tid; i < NF / 4; i += 256) crow[i] = z;
    }
    __syncthreads();

    // ---- p6b: rank (idx tiebreak) + scatter winners ----
    for (int j = tid; j < C; j += 256) {
        float v = sval[j];
        int myi = sidxA[j];
        int rank = 0;
        for (int t = 0; t < C; t++) {
            float vt = sval[t];
            rank += (vt > v) || (vt == v && sidxA[t] < myi);
        }
        if (rank < TOPK) {
            stki[rank] = myi;
            stkv[rank] = v;
            codes[(size_t)row * NF + myi] = v;
        }
    }
    __syncthreads();

    // ---- p6c: sparse decode (float4, 192 threads) ----
    if (tid < DM / 4) {
        float4 a = make_float4(0.f, 0.f, 0.f, 0.f);
#pragma unroll 4
        for (int k = 0; k < TOPK; k++) {
            const float4* dr = (const float4*)(Dm + (size_t)stki[k] * DM);
            float4 d = dr[tid];
            float v = stkv[k];
            a.x = fmaf(v, d.x, a.x); a.y = fmaf(v, d.y, a.y);
            a.z = fmaf(v, d.z, a.z); a.w = fmaf(v, d.w, a.w);
        }
        ((float4*)(recon + (size_t)row * DM))[tid] = a;
    }
}

// ============================================================
// launch
// ============================================================
extern "C" void kernel_launch(void* const* d_in, const int* in_sizes, int n_in,
                              void* d_out, int out_size) {
    const float* x    = (const float*)d_in[0];
    const float* Wenc = (const float*)d_in[1];
    const float* benc = (const float*)d_in[2];
    const float* Dm   = (const float*)d_in[3];

    float* out   = (float*)d_out;
    float* recon = out;
    float* codes = out + (size_t)M_ROWS * DM;
    float* pre   = codes + (size_t)M_ROWS * NF;

    cudaFuncSetAttribute(gemm_mma_kernel,
                         cudaFuncAttributeMaxDynamicSharedMemorySize, GEMM_SMEM);

    convert_x_kernel<<<(M_ROWS * KDIM / 4 + 255) / 256, 256>>>(x);
    convert_w_kernel<<<(NF * KDIM / 4 + 255) / 256, 256>>>(Wenc);
    {
        dim3 grid(M_ROWS / BM, NF / BN);
        gemm_mma_kernel<<<grid, 256, GEMM_SMEM>>>(benc, pre);
    }
    postgemm_kernel<<<M_ROWS, 256>>>(pre, x, Wenc, benc, Dm, codes, recon);
}

// round 13
// speedup vs baseline: 1.7168x; 1.7168x over previous
#include <cuda_runtime.h>
#include <cuda_fp16.h>
#include <stdint.h>

#define M_ROWS   8192
#define DM       768
#define NF       16384
#define TOPK     64
#define TOPC     128
#define KDIM     768
#define CAND_MAX 1024
#define AMB_CAP  128

// ---------------- scratch (__device__ globals; no allocs) ----------------
__device__ __align__(256) __half g_A[M_ROWS * KDIM];   // 12.6 MB
__device__ __align__(256) __half g_B[NF     * KDIM];   // 25.2 MB

// ---------------- helpers ----------------
__device__ __forceinline__ uint32_t smem_u32(const void* p) {
    uint32_t a;
    asm("{ .reg .u64 t; cvta.to.shared.u64 t, %1; cvt.u32.u64 %0, t; }" : "=r"(a) : "l"(p));
    return a;
}
__device__ __forceinline__ void cp_async16(uint32_t dst, const void* src) {
    asm volatile("cp.async.cg.shared.global [%0], [%1], 16;" :: "r"(dst), "l"(src));
}
#define CP_COMMIT() asm volatile("cp.async.commit_group;" ::: "memory")
#define CP_WAIT(n)  asm volatile("cp.async.wait_group %0;" :: "n"(n) : "memory")

__device__ __forceinline__ void mma16816(float* c,
                                         uint32_t a0, uint32_t a1, uint32_t a2, uint32_t a3,
                                         uint32_t b0, uint32_t b1) {
    asm volatile("mma.sync.aligned.m16n8k16.row.col.f32.f16.f16.f32 "
        "{%0,%1,%2,%3}, {%4,%5,%6,%7}, {%8,%9}, {%0,%1,%2,%3};"
        : "+f"(c[0]), "+f"(c[1]), "+f"(c[2]), "+f"(c[3])
        : "r"(a0), "r"(a1), "r"(a2), "r"(a3), "r"(b0), "r"(b1));
}
__device__ __forceinline__ void ldsm_x4(uint32_t& r0, uint32_t& r1,
                                        uint32_t& r2, uint32_t& r3, uint32_t addr) {
    asm volatile("ldmatrix.sync.aligned.m8n8.x4.shared.b16 {%0,%1,%2,%3}, [%4];"
        : "=r"(r0), "=r"(r1), "=r"(r2), "=r"(r3) : "r"(addr));
}
__device__ __forceinline__ void ldsm_x2(uint32_t& r0, uint32_t& r1, uint32_t addr) {
    asm volatile("ldmatrix.sync.aligned.m8n8.x2.shared.b16 {%0,%1}, [%2];"
        : "=r"(r0), "=r"(r1) : "r"(addr));
}
__device__ __forceinline__ unsigned fkey(unsigned b) {
    return (b & 0x80000000u) ? ~b : (b | 0x80000000u);
}

// ============================================================
// convert: fp32 -> fp16, vectorized x4
// ============================================================
__global__ void convert_x_kernel(const float* __restrict__ x) {
    int i = blockIdx.x * blockDim.x + threadIdx.x;
    if (i >= M_ROWS * KDIM / 4) return;
    float4 v = ((const float4*)x)[i];
    ((__half2*)g_A)[i * 2]     = __floats2half2_rn(v.x, v.y);
    ((__half2*)g_A)[i * 2 + 1] = __floats2half2_rn(v.z, v.w);
}
__global__ void convert_w_kernel(const float* __restrict__ w) {
    int i = blockIdx.x * blockDim.x + threadIdx.x;
    if (i >= NF * KDIM / 4) return;
    float4 v = ((const float4*)w)[i];
    ((__half2*)g_B)[i * 2]     = __floats2half2_rn(v.x, v.y);
    ((__half2*)g_B)[i * 2 + 1] = __floats2half2_rn(v.z, v.w);
}

// ============================================================
// mma.sync fp16 GEMM, 4-stage watertight pipeline + ldmatrix
// (validated R12; ~686us)
// ============================================================
#define BM 128
#define BN 128
#define BK 32
#define STAGES 4
#define ROWB 80
#define STG (256 * ROWB)
#define GEMM_SMEM (STAGES * STG)       // 81920 B
#define KITERS (KDIM / BK)             // 24

__global__ __launch_bounds__(256, 2)
void gemm_mma_kernel(const float* __restrict__ bias, float* __restrict__ pre) {
    extern __shared__ char sm[];
    const uint32_t sb = smem_u32(sm);
    const int tid = threadIdx.x;
    const int wid = tid >> 5;
    const int lane = tid & 31;
    const int g   = lane >> 2;
    const int tig = lane & 3;
    const int bm = blockIdx.x * BM;
    const int bn = blockIdx.y * BN;
    const int wm = (wid >> 2) * 64;
    const int wn = (wid & 3) * 32;

    const __half* Ag = g_A + (size_t)bm * KDIM;
    const __half* Bg = g_B + (size_t)bn * KDIM;

    float acc[4][4][4];
#pragma unroll
    for (int mi = 0; mi < 4; mi++)
#pragma unroll
        for (int ni = 0; ni < 4; ni++)
#pragma unroll
            for (int q = 0; q < 4; q++) acc[mi][ni][q] = 0.f;

    const int lr0 = tid >> 2;
    const int lr1 = (tid + 256) >> 2;
    const int lc  = tid & 3;

    auto issue = [&](int s) {
        const uint32_t base = sb + (s % STAGES) * STG;
        const size_t k0 = (size_t)s * BK;
        cp_async16(base + lr0 * ROWB + lc * 16, Ag + (size_t)lr0 * KDIM + k0 + lc * 8);
        cp_async16(base + lr1 * ROWB + lc * 16, Ag + (size_t)lr1 * KDIM + k0 + lc * 8);
        const uint32_t bb = base + 128 * ROWB;
        cp_async16(bb + lr0 * ROWB + lc * 16, Bg + (size_t)lr0 * KDIM + k0 + lc * 8);
        cp_async16(bb + lr1 * ROWB + lc * 16, Bg + (size_t)lr1 * KDIM + k0 + lc * 8);
    };

    issue(0); CP_COMMIT();
    issue(1); CP_COMMIT();
    issue(2); CP_COMMIT();

    const uint32_t a_lrow = (uint32_t)(lane & 15) * ROWB + ((lane >> 4) & 1) * 16;
    const uint32_t b_lrow = (uint32_t)(lane & 7)  * ROWB + ((lane >> 3) & 1) * 16;

    for (int kb = 0; kb < KITERS; kb++) {
        if (kb + 3 < KITERS) issue(kb + 3);
        CP_COMMIT();
        CP_WAIT(3);
        __syncthreads();

        const uint32_t abase = sb + (kb % STAGES) * STG;
        const uint32_t bbase = abase + 128 * ROWB;
#pragma unroll
        for (int kk = 0; kk < 2; kk++) {
            uint32_t bfr[4][2];
#pragma unroll
            for (int ni = 0; ni < 4; ni++)
                ldsm_x2(bfr[ni][0], bfr[ni][1],
                        bbase + (wn + ni * 8) * ROWB + kk * 32 + b_lrow);
#pragma unroll
            for (int mi = 0; mi < 4; mi++) {
                uint32_t a0, a1, a2, a3;
                ldsm_x4(a0, a1, a2, a3,
                        abase + (wm + mi * 16) * ROWB + kk * 32 + a_lrow);
#pragma unroll
                for (int ni = 0; ni < 4; ni++)
                    mma16816(acc[mi][ni], a0, a1, a2, a3, bfr[ni][0], bfr[ni][1]);
            }
        }
        __syncthreads();
    }

#pragma unroll
    for (int ni = 0; ni < 4; ni++) {
        const int col = bn + wn + ni * 8 + tig * 2;
        float2 bz = *(const float2*)(bias + col);
#pragma unroll
        for (int mi = 0; mi < 4; mi++) {
            const int r0 = bm + wm + mi * 16 + g;
            float2 v0, v1;
            v0.x = acc[mi][ni][0] + bz.x; v0.y = acc[mi][ni][1] + bz.y;
            v1.x = acc[mi][ni][2] + bz.x; v1.y = acc[mi][ni][3] + bz.y;
            *(float2*)(pre + (size_t)r0 * NF + col)       = v0;
            *(float2*)(pre + (size_t)(r0 + 8) * NF + col) = v1;
        }
    }
}

// ============================================================
// FUSED post-GEMM v5 (one block/row):
//   p1: stream pre (float4) -> coarse 12-bit hist
//   p2: pivot -> collect top-~160 (val, idx)
//   p3: approx rank -> v64 (64th approx value)
//   p4: definite winners: a > v64+DW (approx values, proven-in)
//       ambiguous window |a - v64| <= DW: exact fp32 rescore
//       (validated ascending-k chain) for ~2 rows only
//   p5: zero codes row; scatter winners; sparse decode (float4)
// ============================================================
__global__ __launch_bounds__(256)
void postgemm_kernel(const float* __restrict__ pre,
                     const float* __restrict__ x,
                     const float* __restrict__ Wenc,
                     const float* __restrict__ benc,
                     const float* __restrict__ Dm,
                     float* __restrict__ codes,
                     float* __restrict__ recon) {
    __shared__ float    xs[DM];
    __shared__ unsigned hist[4096];
    __shared__ float    sval[CAND_MAX];
    __shared__ int      sidx[CAND_MAX];
    __shared__ int      srank[CAND_MAX];
    __shared__ float    aval[AMB_CAP];
    __shared__ int      aidx[AMB_CAP];
    __shared__ int      stki[TOPK];
    __shared__ float    stkv[TOPK];
    __shared__ unsigned wsum[8];
    __shared__ unsigned s_pv, s_chi, s_cnt, s_amb, s_m;
    __shared__ float    s_v64;
    __shared__ int      s_lvl2;

    const int row = blockIdx.x;
    const int tid = threadIdx.x;
    const int wid = tid >> 5;
    const int lane = tid & 31;
    const float4* p4 = (const float4*)(pre + (size_t)row * NF);

    // ---- p1: zero hist; coarse 12-bit hist; load x ----
#pragma unroll
    for (int q = 0; q < 16; q++) hist[tid + q * 256] = 0u;
    if (tid == 0) { s_cnt = 0u; s_amb = 0u; s_m = 0u; s_lvl2 = 0; }
    __syncthreads();

    for (int i = tid; i < NF / 4; i += 256) {
        float4 v = p4[i];
        atomicAdd(&hist[fkey(__float_as_uint(v.x)) >> 20], 1u);
        atomicAdd(&hist[fkey(__float_as_uint(v.y)) >> 20], 1u);
        atomicAdd(&hist[fkey(__float_as_uint(v.z)) >> 20], 1u);
        atomicAdd(&hist[fkey(__float_as_uint(v.w)) >> 20], 1u);
    }
    for (int i = tid; i < DM; i += 256) xs[i] = x[(size_t)row * DM + i];
    __syncthreads();

    // ---- pivot scan over 4096 bins, descending ----
    auto pivot4096 = [&](unsigned want) {
        unsigned h[16], csum = 0;
        const int hi = 4095 - 16 * tid;
#pragma unroll
        for (int q = 0; q < 16; q++) { h[q] = hist[hi - q]; csum += h[q]; }
        unsigned incl = csum;
#pragma unroll
        for (int o = 1; o < 32; o <<= 1) {
            unsigned n = __shfl_up_sync(0xffffffffu, incl, o);
            if (lane >= o) incl += n;
        }
        if (lane == 31) wsum[wid] = incl;
        __syncthreads();
        if (wid == 0 && lane < 8) {
            unsigned w = wsum[lane];
#pragma unroll
            for (int o = 1; o < 8; o <<= 1) {
                unsigned n = __shfl_up_sync(0x000000ffu, w, o);
                if (lane >= o) w += n;
            }
            wsum[lane] = w;
        }
        __syncthreads();
        incl += (wid > 0 ? wsum[wid - 1] : 0u);
        unsigned excl = incl - csum;
        if (excl < want && want <= incl) {
            unsigned run = excl;
#pragma unroll
            for (int q = 0; q < 16; q++) {
                if (run < want && want <= run + h[q]) {
                    s_pv = (unsigned)(hi - q);
                    s_chi = run;
                }
                run += h[q];
            }
        }
        __syncthreads();
    };

    pivot4096(TOPC);
    const unsigned pv1 = s_pv;
    const unsigned chi = s_chi;
    const unsigned cb  = hist[pv1];
    __syncthreads();

    // ultra-rare fat-bin refinement (keeps C <= CAND_MAX)
    unsigned pv2 = 0u;
    if (chi + cb > CAND_MAX) {
#pragma unroll
        for (int q = 0; q < 16; q++) hist[tid + q * 256] = 0u;
        __syncthreads();
        for (int i = tid; i < NF; i += 256) {
            unsigned k = fkey(__float_as_uint(pre[(size_t)row * NF + i]));
            if ((k >> 20) == pv1) atomicAdd(&hist[(k >> 8) & 0xfffu], 1u);
        }
        __syncthreads();
        pivot4096(TOPC - chi);
        pv2 = s_pv;
        if (tid == 0) s_lvl2 = 1;
        __syncthreads();
    }
    const int lvl2 = s_lvl2;

    // ---- p2: collect (val, idx) ----
    for (int i = tid; i < NF / 4; i += 256) {
        float4 v = p4[i];
        float fv[4] = {v.x, v.y, v.z, v.w};
#pragma unroll
        for (int c = 0; c < 4; c++) {
            unsigned k = fkey(__float_as_uint(fv[c]));
            unsigned b = k >> 20;
            bool take = (b > pv1) ||
                        (b == pv1 && (!lvl2 || ((k >> 8) & 0xfffu) >= pv2));
            if (take) {
                unsigned s = atomicAdd(&s_cnt, 1u);
                if (s < CAND_MAX) { sval[s] = fv[c]; sidx[s] = i * 4 + c; }
            }
        }
    }

    // zero codes row (fire-and-forget; ordered before scatter by barrier)
    {
        float4* crow = (float4*)(codes + (size_t)row * NF);
        float4 z = make_float4(0.f, 0.f, 0.f, 0.f);
        for (int i = tid; i < NF / 4; i += 256) crow[i] = z;
    }
    __syncthreads();
    const int C = (int)min(s_cnt, (unsigned)CAND_MAX);

    // ---- p3: approx rank (idx tiebreak) + find v64 ----
    for (int j = tid; j < C; j += 256) {
        float v = sval[j];
        int myi = sidx[j];
        int rank = 0;
        for (int t = 0; t < C; t++) {
            float vt = sval[t];
            rank += (vt > v) || (vt == v && sidx[t] < myi);
        }
        srank[j] = rank;
        if (rank == TOPK - 1) s_v64 = v;
    }
    __syncthreads();
    const float v64 = s_v64;
    const float DW = 8e-3f;

    // ---- p4a: classify; emit definite winners (approx values) ----
    for (int j = tid; j < C; j += 256) {
        float a = sval[j];
        if (a > v64 + DW) {
            atomicAdd(&s_m, 1u);
            int slot = srank[j];              // definite = top-m by approx
            stki[slot] = sidx[j];
            stkv[slot] = a;
            codes[(size_t)row * NF + sidx[j]] = a;
        } else if (a >= v64 - DW) {
            unsigned s = atomicAdd(&s_amb, 1u);
            if (s < AMB_CAP) aidx[s] = sidx[j];
        }
    }
    __syncthreads();
    const int m = (int)s_m;
    const int ambC = (int)min(s_amb, (unsigned)AMB_CAP);
    const int rleft = TOPK - m;

    // ---- p4b: exact fp32 rescore of ambiguous (~2 rows) ----
    for (int t = tid; t < ambC; t += 256) {
        const int idx = aidx[t];
        const float4* wr = (const float4*)(Wenc + (size_t)idx * DM);
        float acc = 0.f;
#pragma unroll 4
        for (int q = 0; q < DM / 4; q++) {
            float4 w = wr[q];
            acc = fmaf(xs[q * 4 + 0], w.x, acc);
            acc = fmaf(xs[q * 4 + 1], w.y, acc);
            acc = fmaf(xs[q * 4 + 2], w.z, acc);
            acc = fmaf(xs[q * 4 + 3], w.w, acc);
        }
        aval[t] = acc + benc[idx];
    }
    __syncthreads();

    // ---- p4c: rank ambiguous by exact score; emit remaining ----
    for (int t = tid; t < ambC; t += 256) {
        float v = aval[t];
        int myi = aidx[t];
        int rk = 0;
        for (int u = 0; u < ambC; u++) {
            float vu = aval[u];
            rk += (vu > v) || (vu == v && aidx[u] < myi);
        }
        if (rk < rleft) {
            int slot = m + rk;
            stki[slot] = myi;
            stkv[slot] = v;
            codes[(size_t)row * NF + myi] = v;
        }
    }
    __syncthreads();

    // ---- p5: sparse decode (float4, 192 threads) ----
    if (tid < DM / 4) {
        float4 a = make_float4(0.f, 0.f, 0.f, 0.f);
#pragma unroll 4
        for (int k = 0; k < TOPK; k++) {
            const float4* dr = (const float4*)(Dm + (size_t)stki[k] * DM);
            float4 d = dr[tid];
            float v = stkv[k];
            a.x = fmaf(v, d.x, a.x); a.y = fmaf(v, d.y, a.y);
            a.z = fmaf(v, d.z, a.z); a.w = fmaf(v, d.w, a.w);
        }
        ((float4*)(recon + (size_t)row * DM))[tid] = a;
    }
}

// ============================================================
// launch
// ============================================================
extern "C" void kernel_launch(void* const* d_in, const int* in_sizes, int n_in,
                              void* d_out, int out_size) {
    const float* x    = (const float*)d_in[0];
    const float* Wenc = (const float*)d_in[1];
    const float* benc = (const float*)d_in[2];
    const float* Dm   = (const float*)d_in[3];

    float* out   = (float*)d_out;
    float* recon = out;
    float* codes = out + (size_t)M_ROWS * DM;
    float* pre   = codes + (size_t)M_ROWS * NF;

    cudaFuncSetAttribute(gemm_mma_kernel,
                         cudaFuncAttributeMaxDynamicSharedMemorySize, GEMM_SMEM);

    convert_x_kernel<<<(M_ROWS * KDIM / 4 + 255) / 256, 256>>>(x);
    convert_w_kernel<<<(NF * KDIM / 4 + 255) / 256, 256>>>(Wenc);
    {
        dim3 grid(M_ROWS / BM, NF / BN);
        gemm_mma_kernel<<<grid, 256, GEMM_SMEM>>>(benc, pre);
    }
    postgemm_kernel<<<M_ROWS, 256>>>(pre, x, Wenc, benc, Dm, codes, recon);
}